// round 3
// baseline (speedup 1.0000x reference)
#include <cuda_runtime.h>
#include <cuda_bf16.h>

// Erosion2d: out[n,c,y,x] = 3x3 windowed min (pad 1e9) over (16,64,256,256) fp32.
// Separable min. R3 layout: one warp owns a 128-wide x 32-high chunk; each lane
// holds ONE float4 per row (x = 4*lane + 128*chunk). Horizontal 3-min needs just
// 2 shuffles + one uniform 4B seam load. Vertical 3-min via rolling register
// pipeline with prefetch depth 2. Regs capped at 48 -> 40 warps/SM.

#define EH 256
#define EW 256
#define STRIPS 8
#define ROWS_PER_STRIP (EH / STRIPS)

__device__ __forceinline__ float fmin3(float a, float b, float c) {
    return fminf(a, fminf(b, c));
}

__device__ __forceinline__ float4 load_row4(const float* __restrict__ src, int y,
                                            int off) {
    if ((unsigned)y < (unsigned)EH) {
        return *reinterpret_cast<const float4*>(src + (size_t)y * EW + off);
    }
    const float inf = __int_as_float(0x7f800000);
    return make_float4(inf, inf, inf, inf);
}

__device__ __forceinline__ float load_edge(const float* __restrict__ src, int y,
                                           int eoff) {
    if ((unsigned)y < (unsigned)EH) {
        return __ldg(src + (size_t)y * EW + eoff);
    }
    return __int_as_float(0x7f800000);
}

// Horizontal 3-tap min over a 128-wide chunk. Lane l holds x=[4l,4l+4) within
// the chunk. `e` is the out-of-chunk neighbor (x=128 for chunk 0 seen by lane
// 31, x=127 for chunk 1 seen by lane 0); `inf` fills the true image border.
__device__ __forceinline__ float4 hmin_row(float4 v, float e, int lane, int chunk) {
    const unsigned FULL = 0xffffffffu;
    const float inf = __int_as_float(0x7f800000);

    float lA = __shfl_up_sync  (FULL, v.w, 1);   // x = 4l-1
    float rA = __shfl_down_sync(FULL, v.x, 1);   // x = 4l+4

    if (lane == 0)  lA = (chunk == 0) ? inf : e;   // x=-1 pad vs x=127 seam
    if (lane == 31) rA = (chunk == 0) ? e : inf;   // x=128 seam vs x=256 pad

    float4 h;
    h.x = fmin3(lA,  v.x, v.y);
    h.y = fmin3(v.x, v.y, v.z);
    h.z = fmin3(v.y, v.z, v.w);
    h.w = fmin3(v.z, v.w, rA);
    return h;
}

__device__ __forceinline__ float4 vmin3(float4 p, float4 q, float4 r) {
    float4 o;
    o.x = fmin3(p.x, q.x, r.x);
    o.y = fmin3(p.y, q.y, r.y);
    o.z = fmin3(p.z, q.z, r.z);
    o.w = fmin3(p.w, q.w, r.w);
    return o;
}

__global__ __launch_bounds__(256, 5)
void Erosion2d_86517821212128_kernel(const float* __restrict__ x,
                                     float* __restrict__ out,
                                     int n_imgs) {
    const int gw    = (int)((blockIdx.x * blockDim.x + threadIdx.x) >> 5);
    const int lane  = (int)(threadIdx.x & 31);
    const int img   = gw >> 4;              // 2 chunks * 8 strips = 16 warps/img
    const int rem   = gw & 15;
    const int chunk = rem & 1;              // low bit: both chunks in same block
    const int strip = rem >> 1;
    if (img >= n_imgs) return;

    const float* src = x   + (size_t)img * (EH * EW);
    float*       dst = out + (size_t)img * (EH * EW);

    const int off  = chunk * 128 + lane * 4;     // this lane's x
    const int eoff = (chunk == 0) ? 128 : 127;   // seam neighbor x

    const int ys = strip * ROWS_PER_STRIP;

    // Pipeline: hA=hmin(y-1), hB=hmin(y); raw rows y+1 (rN,eN), y+2 (rP,eP).
    {
        float4 rm1 = load_row4(src, ys - 1, off);
        float  em1 = load_edge(src, ys - 1, eoff);
        float4 r0  = load_row4(src, ys, off);
        float  e0  = load_edge(src, ys, eoff);
        float4 hA  = hmin_row(rm1, em1, lane, chunk);
        float4 hB  = hmin_row(r0,  e0,  lane, chunk);

        float4 rN = load_row4(src, ys + 1, off);
        float  eN = load_edge(src, ys + 1, eoff);
        float4 rP = load_row4(src, ys + 2, off);
        float  eP = load_edge(src, ys + 2, eoff);

#pragma unroll 4
        for (int yo = ys; yo < ys + ROWS_PER_STRIP; ++yo) {
            float4 rQ = load_row4(src, yo + 3, off);   // prefetch depth 2
            float  eQ = load_edge(src, yo + 3, eoff);
            float4 hC = hmin_row(rN, eN, lane, chunk);
            float4 o  = vmin3(hA, hB, hC);
            __stcs(reinterpret_cast<float4*>(dst + (size_t)yo * EW + off), o);
            hA = hB; hB = hC;
            rN = rP; eN = eP;
            rP = rQ; eP = eQ;
        }
    }
}

extern "C" void kernel_launch(void* const* d_in, const int* in_sizes, int n_in,
                              void* d_out, int out_size) {
    const float* x = (const float*)d_in[0];
    float* out = (float*)d_out;
    const int n_imgs = in_sizes[0] / (EH * EW);            // 1024
    const int total_warps = n_imgs * 2 * STRIPS;           // 16384
    const int threads = 256;                               // 8 warps/block
    const int blocks = (total_warps * 32 + threads - 1) / threads;  // 2048
    Erosion2d_86517821212128_kernel<<<blocks, threads>>>(x, out, n_imgs);
}

// round 4
// speedup vs baseline: 1.0178x; 1.0178x over previous
#include <cuda_runtime.h>
#include <cuda_bf16.h>

// Erosion2d: out[n,c,y,x] = 3x3 windowed min (pad 1e9) over (16,64,256,256) fp32.
// Separable min, R2 layout: one warp owns a full-width (256) x 32-row strip;
// each lane holds 8 pixels/row as two float4s (x=4l and x=128+4l), so every
// LDG/STG is a fully coalesced 1KB-per-row warp stream.
// R4: horizontal exchange uses 4 rotate-shuffles (wrap lanes carry the seam
// values), reg cap 51 (launch_bounds(256,5)) for 40 warps/SM.

#define EH 256
#define EW 256
#define STRIPS 8
#define ROWS_PER_STRIP (EH / STRIPS)

struct Row8 { float4 a, b; };

__device__ __forceinline__ float fmin3(float a, float b, float c) {
    return fminf(a, fminf(b, c));
}

__device__ __forceinline__ Row8 load_row(const float* __restrict__ src, int y,
                                         int o0, int o1) {
    Row8 r;
    if ((unsigned)y < (unsigned)EH) {
        const float* p = src + (size_t)y * EW;
        r.a = *reinterpret_cast<const float4*>(p + o0);
        r.b = *reinterpret_cast<const float4*>(p + o1);
    } else {
        const float inf = __int_as_float(0x7f800000);
        r.a = make_float4(inf, inf, inf, inf);
        r.b = r.a;
    }
    return r;
}

// Horizontal 3-tap min using 4 rotate-shuffles. Lane l holds x=[4l,4l+4) in .a
// and x=[128+4l,128+4l+4) in .b.
//   up_a = a.w from lane l-1 (wrap: lane0 gets a.w[31] = x=127 -> lB seam)
//   dn_a = a.x from lane l+1 (wrap value unused at lane31)
//   up_b = b.w from lane l-1 (wrap value unused at lane0)
//   dn_b = b.x from lane l+1 (wrap: lane31 gets b.x[0] = x=128 -> rA seam)
__device__ __forceinline__ Row8 hmin_row(Row8 v, int lane) {
    const unsigned FULL = 0xffffffffu;
    const float inf = __int_as_float(0x7f800000);

    const int up = (lane + 31) & 31;
    const int dn = (lane + 1) & 31;

    float up_a = __shfl_sync(FULL, v.a.w, up);
    float dn_a = __shfl_sync(FULL, v.a.x, dn);
    float up_b = __shfl_sync(FULL, v.b.w, up);
    float dn_b = __shfl_sync(FULL, v.b.x, dn);

    float lA = (lane == 0)  ? inf  : up_a;   // x = 4l-1      (pad at x=-1)
    float lB = (lane == 0)  ? up_a : up_b;   // x = 128+4l-1  (seam x=127)
    float rA = (lane == 31) ? dn_b : dn_a;   // x = 4l+4      (seam x=128)
    float rB = (lane == 31) ? inf  : dn_b;   // x = 128+4l+4  (pad at x=256)

    Row8 h;
    h.a.x = fmin3(lA,    v.a.x, v.a.y);
    h.a.y = fmin3(v.a.x, v.a.y, v.a.z);
    h.a.z = fmin3(v.a.y, v.a.z, v.a.w);
    h.a.w = fmin3(v.a.z, v.a.w, rA);
    h.b.x = fmin3(lB,    v.b.x, v.b.y);
    h.b.y = fmin3(v.b.x, v.b.y, v.b.z);
    h.b.z = fmin3(v.b.y, v.b.z, v.b.w);
    h.b.w = fmin3(v.b.z, v.b.w, rB);
    return h;
}

__device__ __forceinline__ Row8 vmin3(Row8 p, Row8 q, Row8 r) {
    Row8 o;
    o.a.x = fmin3(p.a.x, q.a.x, r.a.x);
    o.a.y = fmin3(p.a.y, q.a.y, r.a.y);
    o.a.z = fmin3(p.a.z, q.a.z, r.a.z);
    o.a.w = fmin3(p.a.w, q.a.w, r.a.w);
    o.b.x = fmin3(p.b.x, q.b.x, r.b.x);
    o.b.y = fmin3(p.b.y, q.b.y, r.b.y);
    o.b.z = fmin3(p.b.z, q.b.z, r.b.z);
    o.b.w = fmin3(p.b.w, q.b.w, r.b.w);
    return o;
}

__global__ __launch_bounds__(256, 5)
void Erosion2d_86517821212128_kernel(const float* __restrict__ x,
                                     float* __restrict__ out,
                                     int n_imgs) {
    const int gw    = (int)((blockIdx.x * blockDim.x + threadIdx.x) >> 5);
    const int lane  = (int)(threadIdx.x & 31);
    const int img   = gw >> 3;              // STRIPS = 8 warps/img
    const int strip = gw & (STRIPS - 1);
    if (img >= n_imgs) return;

    const float* src = x   + (size_t)img * (EH * EW);
    float*       dst = out + (size_t)img * (EH * EW);

    const int o0 = lane * 4;         // x in [0,128)
    const int o1 = 128 + lane * 4;   // x in [128,256)

    const int ys = strip * ROWS_PER_STRIP;

    // Pipeline: hA = hmin(y-1), hB = hmin(y), rN = raw row y+1.
    Row8 hA = hmin_row(load_row(src, ys - 1, o0, o1), lane);
    Row8 hB = hmin_row(load_row(src, ys,     o0, o1), lane);
    Row8 rN = load_row(src, ys + 1, o0, o1);

#pragma unroll 2
    for (int yo = ys; yo < ys + ROWS_PER_STRIP; ++yo) {
        Row8 rP = load_row(src, yo + 2, o0, o1);   // prefetch next raw row
        Row8 hC = hmin_row(rN, lane);
        Row8 o  = vmin3(hA, hB, hC);
        float* p = dst + (size_t)yo * EW;
        __stcs(reinterpret_cast<float4*>(p + o0), o.a);
        __stcs(reinterpret_cast<float4*>(p + o1), o.b);
        hA = hB;
        hB = hC;
        rN = rP;
    }
}

extern "C" void kernel_launch(void* const* d_in, const int* in_sizes, int n_in,
                              void* d_out, int out_size) {
    const float* x = (const float*)d_in[0];
    float* out = (float*)d_out;
    const int n_imgs = in_sizes[0] / (EH * EW);          // 16*64 = 1024
    const int total_warps = n_imgs * STRIPS;             // 8192
    const int threads = 256;                             // 8 warps/block
    const int blocks = (total_warps * 32 + threads - 1) / threads;  // 1024
    Erosion2d_86517821212128_kernel<<<blocks, threads>>>(x, out, n_imgs);
}

// round 5
// speedup vs baseline: 1.0294x; 1.0114x over previous
#include <cuda_runtime.h>
#include <cuda_bf16.h>

// Erosion2d: out[n,c,y,x] = 3x3 windowed min (pad 1e9) over (16,64,256,256) fp32.
// Separable min, R2 register layout: each lane holds 8 pixels/row as two
// float4s (x=4l and x=128+4l); horizontal 3-min via 4 rotate-shuffles,
// vertical 3-min via rolling register pipeline with prefetch-1.
//
// R5: persistent balanced decomposition. Exactly 592 blocks (148 SM x 4
// co-resident) = 4736 warps = one full residency wave. Each warp owns a
// contiguous range of ~55 GLOBAL rows (flat over all 1024 images x 256 rows),
// resetting the vertical pipeline at image boundaries (warp-uniform branch,
// 1 in 256 rows). Kills the 1.73-wave quantization tail of the fixed-strip grid.

#define EH 256
#define EW 256
#define NSM 148
#define BLOCKS_RES 4
#define NBLOCKS (NSM * BLOCKS_RES)     // 592
#define NWARPS  (NBLOCKS * 8)          // 4736

struct Row8 { float4 a, b; };

__device__ __forceinline__ float fmin3(float a, float b, float c) {
    return fminf(a, fminf(b, c));
}

__device__ __forceinline__ Row8 inf_row() {
    const float inf = __int_as_float(0x7f800000);
    Row8 r;
    r.a = make_float4(inf, inf, inf, inf);
    r.b = r.a;
    return r;
}

// Load global row g (row-major over all images; row stride EW).
__device__ __forceinline__ Row8 load_g(const float* __restrict__ x, int g,
                                       int o0, int o1) {
    const float* p = x + (size_t)g * EW;
    Row8 r;
    r.a = *reinterpret_cast<const float4*>(p + o0);
    r.b = *reinterpret_cast<const float4*>(p + o1);
    return r;
}

__device__ __forceinline__ Row8 load_g_guard(const float* __restrict__ x, int g,
                                             bool valid, int o0, int o1) {
    return valid ? load_g(x, g, o0, o1) : inf_row();
}

// Horizontal 3-tap min using 4 rotate-shuffles. Lane l holds x=[4l,4l+4) in .a
// and x=[128+4l,128+4l+4) in .b. Wrap lanes carry the x=127/128 seam values.
__device__ __forceinline__ Row8 hmin_row(Row8 v, int lane) {
    const unsigned FULL = 0xffffffffu;
    const float inf = __int_as_float(0x7f800000);

    const int up = (lane + 31) & 31;
    const int dn = (lane + 1) & 31;

    float up_a = __shfl_sync(FULL, v.a.w, up);
    float dn_a = __shfl_sync(FULL, v.a.x, dn);
    float up_b = __shfl_sync(FULL, v.b.w, up);
    float dn_b = __shfl_sync(FULL, v.b.x, dn);

    float lA = (lane == 0)  ? inf  : up_a;   // x = 4l-1      (pad at x=-1)
    float lB = (lane == 0)  ? up_a : up_b;   // x = 128+4l-1  (seam x=127)
    float rA = (lane == 31) ? dn_b : dn_a;   // x = 4l+4      (seam x=128)
    float rB = (lane == 31) ? inf  : dn_b;   // x = 128+4l+4  (pad at x=256)

    Row8 h;
    h.a.x = fmin3(lA,    v.a.x, v.a.y);
    h.a.y = fmin3(v.a.x, v.a.y, v.a.z);
    h.a.z = fmin3(v.a.y, v.a.z, v.a.w);
    h.a.w = fmin3(v.a.z, v.a.w, rA);
    h.b.x = fmin3(lB,    v.b.x, v.b.y);
    h.b.y = fmin3(v.b.x, v.b.y, v.b.z);
    h.b.z = fmin3(v.b.y, v.b.z, v.b.w);
    h.b.w = fmin3(v.b.z, v.b.w, rB);
    return h;
}

__device__ __forceinline__ Row8 vmin3(Row8 p, Row8 q, Row8 r) {
    Row8 o;
    o.a.x = fmin3(p.a.x, q.a.x, r.a.x);
    o.a.y = fmin3(p.a.y, q.a.y, r.a.y);
    o.a.z = fmin3(p.a.z, q.a.z, r.a.z);
    o.a.w = fmin3(p.a.w, q.a.w, r.a.w);
    o.b.x = fmin3(p.b.x, q.b.x, r.b.x);
    o.b.y = fmin3(p.b.y, q.b.y, r.b.y);
    o.b.z = fmin3(p.b.z, q.b.z, r.b.z);
    o.b.w = fmin3(p.b.w, q.b.w, r.b.w);
    return o;
}

__global__ __launch_bounds__(256, BLOCKS_RES)
void Erosion2d_86517821212128_kernel(const float* __restrict__ x,
                                     float* __restrict__ out,
                                     int total_rows) {
    const int w    = (int)((blockIdx.x * blockDim.x + threadIdx.x) >> 5);
    const int lane = (int)(threadIdx.x & 31);

    // Balanced contiguous row range for this warp.
    const int g0 = (int)(((long long)w * total_rows) / NWARPS);
    const int g1 = (int)(((long long)(w + 1) * total_rows) / NWARPS);
    if (g0 >= g1) return;

    const int o0 = lane * 4;         // x in [0,128)
    const int o1 = 128 + lane * 4;   // x in [128,256)

    // Pipeline: hA = hmin(row g-1 | inf), hB = hmin(row g), rN = raw row g+1 | inf.
    const int y0 = g0 & (EH - 1);
    Row8 hA = (y0 > 0) ? hmin_row(load_g(x, g0 - 1, o0, o1), lane) : inf_row();
    Row8 hB = hmin_row(load_g(x, g0, o0, o1), lane);
    Row8 rN = load_g_guard(x, g0 + 1, y0 < EH - 1, o0, o1);

    for (int g = g0; g < g1; ++g) {
        // Prefetch raw row g+2: valid iff it's not row 0 of the next image
        // and in bounds (last global row's g+2 would be OOB).
        const bool pf_ok = (((g + 2) & (EH - 1)) != 0) & ((g + 2) < total_rows);
        Row8 rP = load_g_guard(x, g + 2, pf_ok, o0, o1);

        Row8 hC = hmin_row(rN, lane);
        Row8 o  = vmin3(hA, hB, hC);
        float* p = out + (size_t)g * EW;
        __stcs(reinterpret_cast<float4*>(p + o0), o.a);
        __stcs(reinterpret_cast<float4*>(p + o1), o.b);

        if (((g + 1) & (EH - 1)) == 0) {
            // Next row starts a new image: rebuild the pipeline. Warp-uniform,
            // taken once per 256 rows.
            if (g + 1 < g1) {
                hA = inf_row();                              // padding above y=0
                hB = hmin_row(load_g(x, g + 1, o0, o1), lane);
                rN = load_g(x, g + 2, o0, o1);               // y=1, always valid
            }
        } else {
            hA = hB;
            hB = hC;
            rN = rP;
        }
    }
}

extern "C" void kernel_launch(void* const* d_in, const int* in_sizes, int n_in,
                              void* d_out, int out_size) {
    const float* x = (const float*)d_in[0];
    float* out = (float*)d_out;
    const int total_rows = in_sizes[0] / EW;     // 1024 images * 256 rows = 262144
    Erosion2d_86517821212128_kernel<<<NBLOCKS, 256>>>(x, out, total_rows);
}

// round 6
// speedup vs baseline: 1.0367x; 1.0071x over previous
#include <cuda_runtime.h>
#include <cuda_bf16.h>

// Erosion2d: out[n,c,y,x] = 3x3 windowed min (pad 1e9) over (16,64,256,256) fp32.
// Separable min, R2 layout: one warp owns a full-width 256 x 32-row strip;
// each lane holds 8 pixels/row as two float4s (x=4l, x=128+4l).
// R6: row-paired mainloop — each iteration front-batches FOUR independent
// LDG.128 (raw rows y+3, y+4), computes two hmin rows, emits two outputs.
// Doubles per-warp MLP and halves loop/pipeline-shift overhead vs R2.

#define EH 256
#define EW 256
#define STRIPS 8
#define ROWS_PER_STRIP (EH / STRIPS)

struct Row8 { float4 a, b; };

__device__ __forceinline__ float fmin3(float a, float b, float c) {
    return fminf(a, fminf(b, c));
}

__device__ __forceinline__ Row8 inf_row() {
    const float inf = __int_as_float(0x7f800000);
    Row8 r;
    r.a = make_float4(inf, inf, inf, inf);
    r.b = r.a;
    return r;
}

__device__ __forceinline__ Row8 load_row(const float* __restrict__ src, int y,
                                         int o0, int o1) {
    if ((unsigned)y < (unsigned)EH) {
        const float* p = src + (size_t)y * EW;
        Row8 r;
        r.a = *reinterpret_cast<const float4*>(p + o0);
        r.b = *reinterpret_cast<const float4*>(p + o1);
        return r;
    }
    return inf_row();
}

// Horizontal 3-tap min using 4 rotate-shuffles. Lane l holds x=[4l,4l+4) in .a
// and x=[128+4l,128+4l+4) in .b. Wrap lanes carry the x=127/128 seam values.
__device__ __forceinline__ Row8 hmin_row(Row8 v, int lane) {
    const unsigned FULL = 0xffffffffu;
    const float inf = __int_as_float(0x7f800000);

    const int up = (lane + 31) & 31;
    const int dn = (lane + 1) & 31;

    float up_a = __shfl_sync(FULL, v.a.w, up);
    float dn_a = __shfl_sync(FULL, v.a.x, dn);
    float up_b = __shfl_sync(FULL, v.b.w, up);
    float dn_b = __shfl_sync(FULL, v.b.x, dn);

    float lA = (lane == 0)  ? inf  : up_a;   // x = 4l-1      (pad at x=-1)
    float lB = (lane == 0)  ? up_a : up_b;   // x = 128+4l-1  (seam x=127)
    float rA = (lane == 31) ? dn_b : dn_a;   // x = 4l+4      (seam x=128)
    float rB = (lane == 31) ? inf  : dn_b;   // x = 128+4l+4  (pad at x=256)

    Row8 h;
    h.a.x = fmin3(lA,    v.a.x, v.a.y);
    h.a.y = fmin3(v.a.x, v.a.y, v.a.z);
    h.a.z = fmin3(v.a.y, v.a.z, v.a.w);
    h.a.w = fmin3(v.a.z, v.a.w, rA);
    h.b.x = fmin3(lB,    v.b.x, v.b.y);
    h.b.y = fmin3(v.b.x, v.b.y, v.b.z);
    h.b.z = fmin3(v.b.y, v.b.z, v.b.w);
    h.b.w = fmin3(v.b.z, v.b.w, rB);
    return h;
}

__device__ __forceinline__ Row8 vmin3(Row8 p, Row8 q, Row8 r) {
    Row8 o;
    o.a.x = fmin3(p.a.x, q.a.x, r.a.x);
    o.a.y = fmin3(p.a.y, q.a.y, r.a.y);
    o.a.z = fmin3(p.a.z, q.a.z, r.a.z);
    o.a.w = fmin3(p.a.w, q.a.w, r.a.w);
    o.b.x = fmin3(p.b.x, q.b.x, r.b.x);
    o.b.y = fmin3(p.b.y, q.b.y, r.b.y);
    o.b.z = fmin3(p.b.z, q.b.z, r.b.z);
    o.b.w = fmin3(p.b.w, q.b.w, r.b.w);
    return o;
}

__global__ __launch_bounds__(256, 4)
void Erosion2d_86517821212128_kernel(const float* __restrict__ x,
                                     float* __restrict__ out,
                                     int n_imgs) {
    const int gw    = (int)((blockIdx.x * blockDim.x + threadIdx.x) >> 5);
    const int lane  = (int)(threadIdx.x & 31);
    const int img   = gw >> 3;              // STRIPS = 8 warps/img
    const int strip = gw & (STRIPS - 1);
    if (img >= n_imgs) return;

    const float* src = x   + (size_t)img * (EH * EW);
    float*       dst = out + (size_t)img * (EH * EW);

    const int o0 = lane * 4;         // x in [0,128)
    const int o1 = 128 + lane * 4;   // x in [128,256)

    const int ys = strip * ROWS_PER_STRIP;

    // Pipeline state:
    //   hA = hmin(y-1), hB = hmin(y)
    //   rN0, rN1 = raw rows y+1, y+2 (in flight / ready)
    Row8 hA  = hmin_row(load_row(src, ys - 1, o0, o1), lane);
    Row8 hB  = hmin_row(load_row(src, ys,     o0, o1), lane);
    Row8 rN0 = load_row(src, ys + 1, o0, o1);
    Row8 rN1 = load_row(src, ys + 2, o0, o1);

    // 16 paired iterations cover 32 rows.
    for (int yo = ys; yo < ys + ROWS_PER_STRIP; yo += 2) {
        // Front-batch next pair's raw rows: 4 independent LDG.128 in flight
        // while we compute on rN0/rN1.
        Row8 rP0 = load_row(src, yo + 3, o0, o1);
        Row8 rP1 = load_row(src, yo + 4, o0, o1);

        Row8 hC = hmin_row(rN0, lane);
        Row8 hD = hmin_row(rN1, lane);

        Row8 out0 = vmin3(hA, hB, hC);   // row yo
        Row8 out1 = vmin3(hB, hC, hD);   // row yo+1

        float* p0 = dst + (size_t)yo * EW;
        __stcs(reinterpret_cast<float4*>(p0 + o0), out0.a);
        __stcs(reinterpret_cast<float4*>(p0 + o1), out0.b);
        float* p1 = p0 + EW;
        __stcs(reinterpret_cast<float4*>(p1 + o0), out1.a);
        __stcs(reinterpret_cast<float4*>(p1 + o1), out1.b);

        hA = hC; hB = hD;
        rN0 = rP0; rN1 = rP1;
    }
}

extern "C" void kernel_launch(void* const* d_in, const int* in_sizes, int n_in,
                              void* d_out, int out_size) {
    const float* x = (const float*)d_in[0];
    float* out = (float*)d_out;
    const int n_imgs = in_sizes[0] / (EH * EW);          // 16*64 = 1024
    const int total_warps = n_imgs * STRIPS;             // 8192
    const int threads = 256;                             // 8 warps/block
    const int blocks = (total_warps * 32 + threads - 1) / threads;  // 1024
    Erosion2d_86517821212128_kernel<<<blocks, threads>>>(x, out, n_imgs);
}

// round 8
// speedup vs baseline: 1.0837x; 1.0454x over previous
#include <cuda_runtime.h>
#include <cuda_bf16.h>
#include <cstdint>

// Erosion2d: out[n,c,y,x] = 3x3 windowed min (pad 1e9) over (16,64,256,256) fp32.
// Separable min. One warp owns a full-width 256 x 32-row strip; each lane holds
// 8 pixels/row as two float4s (x=4l, x=128+4l). Horizontal 3-min via 4 rotate
// shuffles; vertical 3-min via rolling register pipeline.
//
// R7: raw rows stream GMEM->SMEM via cp.async.cg (register-free MLP) into a
// per-warp 6-row ring. One commit group per row; cp.async.wait_group 4 keeps
// row yo+1 ready each iteration with ~4 rows per warp in flight. OOB rows are
// skipped (empty group) and replaced by +inf after hmin (values discarded).

#define EH 256
#define EW 256
#define STRIPS 8
#define ROWS_PER_STRIP (EH / STRIPS)
#define RING 6
#define WARPS_PER_BLOCK 8
#define ROW_BYTES (EW * 4)

struct Row8 { float4 a, b; };

__device__ __forceinline__ float fmin3(float a, float b, float c) {
    return fminf(a, fminf(b, c));
}

__device__ __forceinline__ Row8 inf_row() {
    const float inf = __int_as_float(0x7f800000);
    Row8 r;
    r.a = make_float4(inf, inf, inf, inf);
    r.b = r.a;
    return r;
}

// Issue async copy of row r into ring slot (1KB: lane l copies bytes
// [16l,16l+16) and [512+16l,512+16l+16) — each lane later reads back exactly
// the bytes it copied, so per-thread wait_group ordering suffices).
__device__ __forceinline__ void issue_row(const float* __restrict__ src, int r,
                                          unsigned int slot_addr, int lane,
                                          bool valid) {
    if (valid) {
        const float* g = src + (size_t)r * EW + lane * 4;
        unsigned int d = slot_addr + lane * 16;
        asm volatile("cp.async.cg.shared.global [%0], [%1], 16;\n"
                     :: "r"(d), "l"(g) : "memory");
        asm volatile("cp.async.cg.shared.global [%0], [%1], 16;\n"
                     :: "r"(d + 512), "l"(g + 128) : "memory");
    }
    asm volatile("cp.async.commit_group;\n" ::: "memory");
}

__device__ __forceinline__ Row8 read_slot(unsigned int slot_addr, int lane) {
    Row8 r;
    unsigned int d = slot_addr + lane * 16;
    asm volatile("ld.shared.v4.f32 {%0,%1,%2,%3}, [%4];"
                 : "=f"(r.a.x), "=f"(r.a.y), "=f"(r.a.z), "=f"(r.a.w) : "r"(d));
    asm volatile("ld.shared.v4.f32 {%0,%1,%2,%3}, [%4];"
                 : "=f"(r.b.x), "=f"(r.b.y), "=f"(r.b.z), "=f"(r.b.w)
                 : "r"(d + 512));
    return r;
}

// Horizontal 3-tap min using 4 rotate-shuffles. Lane l holds x=[4l,4l+4) in .a
// and x=[128+4l,128+4l+4) in .b. Wrap lanes carry the x=127/128 seam values.
__device__ __forceinline__ Row8 hmin_row(Row8 v, int lane) {
    const unsigned FULL = 0xffffffffu;
    const float inf = __int_as_float(0x7f800000);

    const int up = (lane + 31) & 31;
    const int dn = (lane + 1) & 31;

    float up_a = __shfl_sync(FULL, v.a.w, up);
    float dn_a = __shfl_sync(FULL, v.a.x, dn);
    float up_b = __shfl_sync(FULL, v.b.w, up);
    float dn_b = __shfl_sync(FULL, v.b.x, dn);

    float lA = (lane == 0)  ? inf  : up_a;   // x = 4l-1      (pad at x=-1)
    float lB = (lane == 0)  ? up_a : up_b;   // x = 128+4l-1  (seam x=127)
    float rA = (lane == 31) ? dn_b : dn_a;   // x = 4l+4      (seam x=128)
    float rB = (lane == 31) ? inf  : dn_b;   // x = 128+4l+4  (pad at x=256)

    Row8 h;
    h.a.x = fmin3(lA,    v.a.x, v.a.y);
    h.a.y = fmin3(v.a.x, v.a.y, v.a.z);
    h.a.z = fmin3(v.a.y, v.a.z, v.a.w);
    h.a.w = fmin3(v.a.z, v.a.w, rA);
    h.b.x = fmin3(lB,    v.b.x, v.b.y);
    h.b.y = fmin3(v.b.x, v.b.y, v.b.z);
    h.b.z = fmin3(v.b.y, v.b.z, v.b.w);
    h.b.w = fmin3(v.b.z, v.b.w, rB);
    return h;
}

__device__ __forceinline__ Row8 vmin3(Row8 p, Row8 q, Row8 r) {
    Row8 o;
    o.a.x = fmin3(p.a.x, q.a.x, r.a.x);
    o.a.y = fmin3(p.a.y, q.a.y, r.a.y);
    o.a.z = fmin3(p.a.z, q.a.z, r.a.z);
    o.a.w = fmin3(p.a.w, q.a.w, r.a.w);
    o.b.x = fmin3(p.b.x, q.b.x, r.b.x);
    o.b.y = fmin3(p.b.y, q.b.y, r.b.y);
    o.b.z = fmin3(p.b.z, q.b.z, r.b.z);
    o.b.w = fmin3(p.b.w, q.b.w, r.b.w);
    return o;
}

__global__ __launch_bounds__(256, 4)
void Erosion2d_86517821212128_kernel(const float* __restrict__ x,
                                     float* __restrict__ out,
                                     int n_imgs) {
    __shared__ float ring[WARPS_PER_BLOCK][RING][EW];   // 48 KB

    const int gw    = (int)((blockIdx.x * blockDim.x + threadIdx.x) >> 5);
    const int wib   = (int)(threadIdx.x >> 5);
    const int lane  = (int)(threadIdx.x & 31);
    const int img   = gw >> 3;              // STRIPS = 8 warps/img
    const int strip = gw & (STRIPS - 1);
    if (img >= n_imgs) return;

    const float* src = x   + (size_t)img * (EH * EW);
    float*       dst = out + (size_t)img * (EH * EW);

    const int o0 = lane * 4;         // x in [0,128)
    const int o1 = 128 + lane * 4;   // x in [128,256)

    const int ys = strip * ROWS_PER_STRIP;
    const int last_needed = ys + ROWS_PER_STRIP;   // row ys+32 (rN of last iter)

    const unsigned int ring0 =
        (unsigned int)__cvta_generic_to_shared(&ring[wib][0][0]);

    // Prologue: rows ys-1 .. ys+4 into slots 0..5 (row r -> slot r-(ys-1)).
    // Only ys-1 can be OOB at the top; prologue rows never exceed ys+4 <= 228.
#pragma unroll
    for (int k = 0; k < RING; ++k) {
        const int r = ys - 1 + k;
        issue_row(src, r, ring0 + k * ROW_BYTES, lane, r >= 0);
    }

    // Wait until rows ys-1, ys are ready (6 groups committed, <=4 pending).
    asm volatile("cp.async.wait_group 4;\n" ::: "memory");

    Row8 hA = (ys > 0) ? hmin_row(read_slot(ring0, lane), lane) : inf_row();
    Row8 hB = hmin_row(read_slot(ring0 + 1 * ROW_BYTES, lane), lane);

    int sP = 0;   // slot for produced row ys+5+j  ((6+j) % RING)
    int sC = 2;   // slot for consumed row ys+1+j  ((2+j) % RING)

    for (int yo = ys; yo < ys + ROWS_PER_STRIP; ++yo) {
        // Issue row yo+5 (gated: only rows the strip actually needs).
        const int rp = yo + 5;
        issue_row(src, rp, ring0 + sP * ROW_BYTES, lane,
                  (rp <= last_needed) & (rp < EH));

        // Guarantee row yo+1 has landed (<=4 groups pending).
        asm volatile("cp.async.wait_group 4;\n" ::: "memory");

        const bool nvalid = (yo + 1) < EH;
        Row8 hC = nvalid ? hmin_row(read_slot(ring0 + sC * ROW_BYTES, lane), lane)
                         : inf_row();

        Row8 o = vmin3(hA, hB, hC);
        float* p = dst + (size_t)yo * EW;
        __stcs(reinterpret_cast<float4*>(p + o0), o.a);
        __stcs(reinterpret_cast<float4*>(p + o1), o.b);

        hA = hB;
        hB = hC;
        sP = (sP == RING - 1) ? 0 : sP + 1;
        sC = (sC == RING - 1) ? 0 : sC + 1;
    }
}

extern "C" void kernel_launch(void* const* d_in, const int* in_sizes, int n_in,
                              void* d_out, int out_size) {
    const float* x = (const float*)d_in[0];
    float* out = (float*)d_out;
    const int n_imgs = in_sizes[0] / (EH * EW);          // 16*64 = 1024
    const int total_warps = n_imgs * STRIPS;             // 8192
    const int threads = 256;                             // 8 warps/block
    const int blocks = (total_warps * 32 + threads - 1) / threads;  // 1024
    Erosion2d_86517821212128_kernel<<<blocks, threads>>>(x, out, n_imgs);
}